// round 14
// baseline (speedup 1.0000x reference)
#include <cuda_runtime.h>
#include <cuda_bf16.h>

// MergedEmbeddingBag: weights [T,N,D] f32, indices [T,TOTAL] i32, offsets [T,B] i32
// out [T,B,D] f32, sum pooling. T=8, N=100000, D=128, B=16384, L=20.
//
// FINAL CHAMPION (R6), frozen. Warp-per-bag, float4 __ldg gathers,
// shfl-distributed indices, no smem/no barriers, __stcs evict-first output.
//
// Session conclusions (8 confirming runs):
//  - Operates at the B300 LTS chip cap (~12.5 TB/s sustained SM<->L2,
//    path-independent): 1.39 GB compulsory gather traffic -> ~111 us floor.
//    Fast-mode samples: {111.1, 111.7, 112.3, 112.5, 113.6, 113.7} us.
//  - Occupancy (42-67%), persistent-warp pipelining, cache-policy asm, ILP
//    restructuring: all neutral-or-negative. Traffic is irreducible
//    (dup ~0.2%, 51 MB working set >> L1, scatter moves the same bytes,
//    LTS cap is load-path-independent so TMA/cp.async don't help).
//  - The simple "shfl -> __ldg -> fadd" unrolled body is what ptxas
//    front-batches into ~20 consecutive independent LDG.128 per warp;
//    restructuring the hot loop destroys that batching (-17..20%).
//  - Brokered pool is bimodal: identical binaries sample ~111-114 us (fast
//    mode) or ~133 us (slow mode) with identical DRAM byte counts.

#define EB_T 8
#define EB_N 100000
#define EB_D 128
#define EB_B 16384
#define EB_LOG2_B 14
#define FULLMASK 0xffffffffu

__global__ void __launch_bounds__(256, 4)
merged_embeddingbag_warp_kernel(const float* __restrict__ weights,
                                const int* __restrict__ indices,
                                const int* __restrict__ offsets,
                                float* __restrict__ out,
                                int total_per_table)
{
    const int gw   = blockIdx.x * (blockDim.x >> 5) + (threadIdx.x >> 5); // (tbl,bag)
    const int lane = threadIdx.x & 31;
    const int tbl  = gw >> EB_LOG2_B;
    const int bag  = gw & (EB_B - 1);

    const int* off_t = offsets + tbl * EB_B;
    const int start = __ldg(&off_t[bag]);
    const int end   = (bag + 1 < EB_B) ? __ldg(&off_t[bag + 1]) : total_per_table;
    int cnt = end - start;
    if (cnt < 0) cnt = 0;

    const int* idx_t = indices + (size_t)tbl * total_per_table + start;
    const float4* __restrict__ w4 =
        (const float4*)(weights + (size_t)tbl * EB_N * EB_D);

    float4 acc = make_float4(0.f, 0.f, 0.f, 0.f);

    for (int base = 0; base < cnt; base += 32) {
        const int m = min(32, cnt - base);
        // lane j owns index (base+j): one coalesced load, no smem, no sync
        const int myidx = (lane < m) ? __ldg(&idx_t[base + lane]) : 0;

        if (m == 20) {
            // Hot path (fixed L=20): full unroll -> ~20 independent LDG.128
            // in flight per warp (compiler-batched).
            #pragma unroll
            for (int j = 0; j < 20; j++) {
                const int r = __shfl_sync(FULLMASK, myidx, j);
                const float4 v = __ldg(&w4[r * 32 + lane]);
                acc.x += v.x; acc.y += v.y; acc.z += v.z; acc.w += v.w;
            }
        } else {
            for (int j = 0; j < m; j++) {
                const int r = __shfl_sync(FULLMASK, myidx, j);
                const float4 v = __ldg(&w4[r * 32 + lane]);
                acc.x += v.x; acc.y += v.y; acc.z += v.z; acc.w += v.w;
            }
        }
    }

    float4* __restrict__ o4 = (float4*)out;
    __stcs(&o4[(size_t)gw * 32 + lane], acc);   // evict-first: protect weight lines in L2
}

extern "C" void kernel_launch(void* const* d_in, const int* in_sizes, int n_in,
                              void* d_out, int out_size)
{
    const float* weights = (const float*)d_in[0];
    const int*   indices = (const int*)d_in[1];
    const int*   offsets = (const int*)d_in[2];
    float*       out     = (float*)d_out;

    const int total_per_table = in_sizes[1] / EB_T;  // 327680

    const int warps_per_block = 8;                   // 256 threads
    const int total_warps = EB_T * EB_B;             // 131072 bags
    const int nblocks = total_warps / warps_per_block;

    merged_embeddingbag_warp_kernel<<<nblocks, warps_per_block * 32>>>(
        weights, indices, offsets, out, total_per_table);
}

// round 15
// speedup vs baseline: 1.0150x; 1.0150x over previous
#include <cuda_runtime.h>
#include <cuda_bf16.h>

// MergedEmbeddingBag: weights [T,N,D] f32, indices [T,TOTAL] i32, offsets [T,B] i32
// out [T,B,D] f32, sum pooling. T=8, N=100000, D=128, B=16384, L=20.
//
// FINAL CHAMPION (R6), frozen. Warp-per-bag, float4 __ldg gathers,
// shfl-distributed indices, no smem/no barriers, __stcs evict-first output.
//
// Session conclusions (9 confirming runs):
//  - Operates at the B300 LTS chip cap (~12.5 TB/s sustained SM<->L2,
//    path-independent): 1.39 GB compulsory gather traffic -> ~111 us floor.
//    Fast-mode samples: {111.1,111.7,112.3,112.5,112.7,113.6,113.7} us.
//  - Occupancy (42-67%), persistent-warp pipelining, cache-policy asm, ILP
//    restructuring: all neutral-or-negative. Traffic is irreducible
//    (dup ~0.2%, 51 MB working set >> L1, scatter moves the same bytes,
//    LTS cap is load-path-independent so TMA/cp.async don't help).
//  - Grid order (table id in high bits of blockIdx) keeps concurrent waves
//    inside one 51 MB table slab -> fits L2, DRAM stays at the compulsory
//    465 MB. Do not interleave tables.
//  - The simple "shfl -> __ldg -> fadd" unrolled body is what ptxas
//    front-batches into ~20 consecutive independent LDG.128 per warp;
//    restructuring the hot loop destroys that batching (-17..20%).
//  - Brokered pool is bimodal: identical binaries sample ~111-114 us (fast
//    mode) or ~133 us (slow mode) with identical DRAM byte counts.

#define EB_T 8
#define EB_N 100000
#define EB_D 128
#define EB_B 16384
#define EB_LOG2_B 14
#define FULLMASK 0xffffffffu

__global__ void __launch_bounds__(256, 4)
merged_embeddingbag_warp_kernel(const float* __restrict__ weights,
                                const int* __restrict__ indices,
                                const int* __restrict__ offsets,
                                float* __restrict__ out,
                                int total_per_table)
{
    const int gw   = blockIdx.x * (blockDim.x >> 5) + (threadIdx.x >> 5); // (tbl,bag)
    const int lane = threadIdx.x & 31;
    const int tbl  = gw >> EB_LOG2_B;
    const int bag  = gw & (EB_B - 1);

    const int* off_t = offsets + tbl * EB_B;
    const int start = __ldg(&off_t[bag]);
    const int end   = (bag + 1 < EB_B) ? __ldg(&off_t[bag + 1]) : total_per_table;
    int cnt = end - start;
    if (cnt < 0) cnt = 0;

    const int* idx_t = indices + (size_t)tbl * total_per_table + start;
    const float4* __restrict__ w4 =
        (const float4*)(weights + (size_t)tbl * EB_N * EB_D);

    float4 acc = make_float4(0.f, 0.f, 0.f, 0.f);

    for (int base = 0; base < cnt; base += 32) {
        const int m = min(32, cnt - base);
        // lane j owns index (base+j): one coalesced load, no smem, no sync
        const int myidx = (lane < m) ? __ldg(&idx_t[base + lane]) : 0;

        if (m == 20) {
            // Hot path (fixed L=20): full unroll -> ~20 independent LDG.128
            // in flight per warp (compiler-batched).
            #pragma unroll
            for (int j = 0; j < 20; j++) {
                const int r = __shfl_sync(FULLMASK, myidx, j);
                const float4 v = __ldg(&w4[r * 32 + lane]);
                acc.x += v.x; acc.y += v.y; acc.z += v.z; acc.w += v.w;
            }
        } else {
            for (int j = 0; j < m; j++) {
                const int r = __shfl_sync(FULLMASK, myidx, j);
                const float4 v = __ldg(&w4[r * 32 + lane]);
                acc.x += v.x; acc.y += v.y; acc.z += v.z; acc.w += v.w;
            }
        }
    }

    float4* __restrict__ o4 = (float4*)out;
    __stcs(&o4[(size_t)gw * 32 + lane], acc);   // evict-first: protect weight lines in L2
}

extern "C" void kernel_launch(void* const* d_in, const int* in_sizes, int n_in,
                              void* d_out, int out_size)
{
    const float* weights = (const float*)d_in[0];
    const int*   indices = (const int*)d_in[1];
    const int*   offsets = (const int*)d_in[2];
    float*       out     = (float*)d_out;

    const int total_per_table = in_sizes[1] / EB_T;  // 327680

    const int warps_per_block = 8;                   // 256 threads
    const int total_warps = EB_T * EB_B;             // 131072 bags
    const int nblocks = total_warps / warps_per_block;

    merged_embeddingbag_warp_kernel<<<nblocks, warps_per_block * 32>>>(
        weights, indices, offsets, out, total_per_table);
}